// round 7
// baseline (speedup 1.0000x reference)
#include <cuda_runtime.h>
#include <cuda_bf16.h>

#define N_SEQ   256
#define M_GENES 2000
#define D_DIM   128
#define N_NUC   4
#define NG      32                         // sequences per warp
#define TOTAL_WORK 2000                    // block-work items (8 warps each)
#define GRID_BLOCKS 1000                   // each block does 2 items -> 1 wave
#define WARPS_PER_BLOCK 8

// One warp-work-item: gene m = wid % 2000, seq group ng = wid / 2000.
__global__ void __launch_bounds__(256) fused_kernel(
        const int* __restrict__ seq,
        const float* __restrict__ emb,
        float* __restrict__ out) {
    // Per-warp private staging: 4 normalized vectors (2 KB/warp)
    __shared__ float s_tab[WARPS_PER_BLOCK][N_NUC * D_DIM];

    const unsigned int warp = threadIdx.x >> 5;
    const unsigned int lane = threadIdx.x & 31u;
    float* s_warp = s_tab[warp];

    #pragma unroll
    for (int item = 0; item < 2; item++) {
        const unsigned int wid = (blockIdx.x + item * GRID_BLOCKS) * WARPS_PER_BLOCK + warp;
        const unsigned int m  = wid % M_GENES;
        const unsigned int ng = wid / M_GENES;       // 0..7
        const unsigned int n0 = ng * NG;

        // ---- Load the 4 candidate vectors for gene m (2 KB contiguous) ----
        const float4* tab = reinterpret_cast<const float4*>(
            emb + (size_t)m * N_NUC * D_DIM);
        float4 v0 = __ldg(tab + 0 * 32 + lane);
        float4 v1 = __ldg(tab + 1 * 32 + lane);
        float4 v2 = __ldg(tab + 2 * 32 + lane);
        float4 v3 = __ldg(tab + 3 * 32 + lane);

        // ---- This warp's 32 sequence indices (one per lane) ----
        int gidx = __ldg(seq + (size_t)(n0 + lane) * M_GENES + m);

        // ---- Normalize in registers (4 interleaved warp allreduces) ----
        float s0 = v0.x*v0.x + v0.y*v0.y + v0.z*v0.z + v0.w*v0.w;
        float s1 = v1.x*v1.x + v1.y*v1.y + v1.z*v1.z + v1.w*v1.w;
        float s2 = v2.x*v2.x + v2.y*v2.y + v2.z*v2.z + v2.w*v2.w;
        float s3 = v3.x*v3.x + v3.y*v3.y + v3.z*v3.z + v3.w*v3.w;
        #pragma unroll
        for (int o = 16; o > 0; o >>= 1) {
            s0 += __shfl_xor_sync(0xffffffffu, s0, o);
            s1 += __shfl_xor_sync(0xffffffffu, s1, o);
            s2 += __shfl_xor_sync(0xffffffffu, s2, o);
            s3 += __shfl_xor_sync(0xffffffffu, s3, o);
        }
        float i0 = 1.0f / fmaxf(sqrtf(s0), 1e-12f);
        float i1 = 1.0f / fmaxf(sqrtf(s1), 1e-12f);
        float i2 = 1.0f / fmaxf(sqrtf(s2), 1e-12f);
        float i3 = 1.0f / fmaxf(sqrtf(s3), 1e-12f);
        v0.x *= i0; v0.y *= i0; v0.z *= i0; v0.w *= i0;
        v1.x *= i1; v1.y *= i1; v1.z *= i1; v1.w *= i1;
        v2.x *= i2; v2.y *= i2; v2.z *= i2; v2.w *= i2;
        v3.x *= i3; v3.y *= i3; v3.z *= i3; v3.w *= i3;

        // ---- Stage to per-warp smem. Each lane writes its own 4 float4s;
        //      the emit loop below reads back ONLY this lane's slots, so no
        //      cross-lane smem dependency -> no sync needed.
        float4* sw = reinterpret_cast<float4*>(s_warp) + lane;
        sw[0 * 32] = v0;
        sw[1 * 32] = v1;
        sw[2 * 32] = v2;
        sw[3 * 32] = v3;

        // ---- Emit 32 rows: shfl idx -> LDS.128 -> STG.128 ----
        float4* dst = reinterpret_cast<float4*>(
            out + ((size_t)n0 * M_GENES + m) * D_DIM) + lane;
        const size_t row_stride = (size_t)M_GENES * (D_DIM / 4);

        #pragma unroll
        for (int nn = 0; nn < NG; nn++) {
            int g = __shfl_sync(0xffffffffu, gidx, nn);
            float4 v = sw[g * 32];              // own-lane LDS.128, no conflicts
            dst[(size_t)nn * row_stride] = v;   // STG.128
        }
    }
}

extern "C" void kernel_launch(void* const* d_in, const int* in_sizes, int n_in,
                              void* d_out, int out_size) {
    const int*   gene_seq = (const int*)d_in[0];     // (256, 2000) int32
    const float* emb      = (const float*)d_in[1];   // (2000, 4, 128) f32
    float*       out      = (float*)d_out;           // (256, 2000, 128) f32

    fused_kernel<<<GRID_BLOCKS, WARPS_PER_BLOCK * 32>>>(gene_seq, emb, out);
}